// round 1
// baseline (speedup 1.0000x reference)
#include <cuda_runtime.h>
#include <cstdint>

// ---------------------------------------------------------------------------
// CFNO collapsed pipeline.
//
// Math: y = Re(IFFT16( FFT256(p) @ W^T + btil )) with W = W_r + i*W_i,
//       btil = (b_r - b_i) + i*(b_r + b_i).
// Since FFT/IFFT are linear:  y[n,k] = sum_j p[n,j] * A[k,j] + c[k]
//   A[k,j] = Re( sum_f M[k,f] e^{-2pi i j f/256} ),
//   M[k,f] = (1/16) sum_d (W_r[d,f] + i W_i[d,f]) e^{+2pi i k d/16}
//   c[k]   = (1/16) sum_d [ (b_r-b_i)_d cos(2pi kd/16) - (b_r+b_i)_d sin(2pi kd/16) ]
// Then depthwise 3x3 conv + bias, train-mode BatchNorm, and the nearest
// interpolation 128->128 is the identity.
// ---------------------------------------------------------------------------

#define BHW  (8 * 16 * 128 * 128)   // 2,097,152 elements (8 MB)

__device__ float g_At[256 * 16];    // A transposed: At[j][k]
__device__ float g_c[16];
__device__ float g_img[BHW];        // linear-stage output [B,16,128,128]
__device__ float g_conved[BHW];     // conv output
__device__ float g_psum[128];       // per-(b,d) partial sums
__device__ float g_psq[128];
__device__ float g_scale[16];
__device__ float g_shift[16];

// ---------------------------------------------------------------------------
// Kernel A: build A^T and c from the weights. 16 blocks (one per k), 256 thr.
// ---------------------------------------------------------------------------
__global__ void kA(const float* __restrict__ Wr, const float* __restrict__ Wi,
                   const float* __restrict__ br, const float* __restrict__ bi)
{
    __shared__ float ct[256], st[256];
    __shared__ float Mr[256], Mi[256];
    const int tid = threadIdx.x;
    const int k = blockIdx.x;

    // twiddle table: e^{2pi i t/256}
    float s, c;
    sincospif(2.0f * (float)tid / 256.0f, &s, &c);
    ct[tid] = c; st[tid] = s;
    __syncthreads();

    // M[k][f], f = tid. e^{+2pi i kd/16} = table[(kd mod 16)*16]
    {
        const int f = tid;
        float mr = 0.f, mi = 0.f;
#pragma unroll
        for (int d = 0; d < 16; d++) {
            const int t = ((k * d) & 15) << 4;
            const float wc = ct[t], ws = st[t];
            const float wr = Wr[d * 256 + f];
            const float wv = Wi[d * 256 + f];
            mr += wr * wc - wv * ws;
            mi += wr * ws + wv * wc;
        }
        Mr[f] = mr * (1.0f / 16.0f);
        Mi[f] = mi * (1.0f / 16.0f);
    }
    __syncthreads();

    // A[k][j] = sum_f Mr[f]*cos(2pi jf/256) + Mi[f]*sin(2pi jf/256), j = tid
    {
        const int j = tid;
        float a0 = 0.f, a1 = 0.f, a2 = 0.f, a3 = 0.f;
#pragma unroll 4
        for (int f = 0; f < 256; f += 4) {
            a0 += Mr[f + 0] * ct[(j * (f + 0)) & 255] + Mi[f + 0] * st[(j * (f + 0)) & 255];
            a1 += Mr[f + 1] * ct[(j * (f + 1)) & 255] + Mi[f + 1] * st[(j * (f + 1)) & 255];
            a2 += Mr[f + 2] * ct[(j * (f + 2)) & 255] + Mi[f + 2] * st[(j * (f + 2)) & 255];
            a3 += Mr[f + 3] * ct[(j * (f + 3)) & 255] + Mi[f + 3] * st[(j * (f + 3)) & 255];
        }
        g_At[j * 16 + k] = (a0 + a1) + (a2 + a3);
    }

    if (tid == 0) {
        float acc = 0.f;
#pragma unroll
        for (int d = 0; d < 16; d++) {
            const int t = ((k * d) & 15) << 4;
            acc += (br[d] - bi[d]) * ct[t] - (br[d] + bi[d]) * st[t];
        }
        g_c[k] = acc * (1.0f / 16.0f);
    }
}

// ---------------------------------------------------------------------------
// Kernel B: patch GEMM. Each thread: 2 horizontally adjacent patches x 16 k.
// 128 threads/block -> 256 patches/block -> 512 blocks.
// A^T broadcast from shared (same-address LDS.128 across the warp).
// ---------------------------------------------------------------------------
__global__ __launch_bounds__(128) void kB(const float* __restrict__ x)
{
    __shared__ float sA[256 * 16];
    __shared__ float sc[16];

    for (int i = threadIdx.x; i < 4096; i += 128) sA[i] = g_At[i];
    if (threadIdx.x < 16) sc[threadIdx.x] = g_c[threadIdx.x];
    __syncthreads();

    const int p0 = blockIdx.x * 256 + threadIdx.x * 2;   // even patch index
    const int b  = p0 >> 14;
    const int ph = (p0 >> 7) & 127;
    const int pw = p0 & 127;

    const float* xp = x + ((size_t)(b * 2048 + ph * 16)) * 2048 + (size_t)pw * 16;

    float acc0[16], acc1[16];
#pragma unroll
    for (int k = 0; k < 16; k++) { acc0[k] = sc[k]; acc1[k] = sc[k]; }

#pragma unroll 1
    for (int s1 = 0; s1 < 16; s1++) {
        const float4* row = (const float4*)(xp + (size_t)s1 * 2048);
        float4 q[8];
#pragma unroll
        for (int i = 0; i < 8; i++) q[i] = row[i];
        const float* p0v = (const float*)&q[0];   // patch pw,   16 floats
        const float* p1v = (const float*)&q[4];   // patch pw+1, 16 floats

#pragma unroll
        for (int s2 = 0; s2 < 16; s2++) {
            const float* Ak = &sA[(s1 * 16 + s2) * 16];
            float4 Aq[4];
#pragma unroll
            for (int kk = 0; kk < 4; kk++) Aq[kk] = ((const float4*)Ak)[kk];
            const float* Af = (const float*)Aq;
            const float v0 = p0v[s2];
            const float v1 = p1v[s2];
#pragma unroll
            for (int k = 0; k < 16; k++) {
                acc0[k] += v0 * Af[k];
                acc1[k] += v1 * Af[k];
            }
        }
    }

    // img[b][k][ph][pw]
    const size_t ob = (size_t)b * 16 * 16384 + (size_t)ph * 128 + (size_t)pw;
#pragma unroll
    for (int k = 0; k < 16; k++) {
        g_img[ob + (size_t)k * 16384]     = acc0[k];
        g_img[ob + (size_t)k * 16384 + 1] = acc1[k];
    }
}

// ---------------------------------------------------------------------------
// Kernel C: depthwise 3x3 conv (SAME, correlation) + bias, with per-(b,d)
// partial sum / sumsq for BatchNorm. 128 blocks (one per plane), 256 threads.
// ---------------------------------------------------------------------------
__global__ void kC(const float* __restrict__ convw, const float* __restrict__ convb)
{
    const int blk = blockIdx.x;              // b*16 + d
    const int d = blk & 15;
    const float* plane = g_img + (size_t)blk * 16384;
    float* outp = g_conved + (size_t)blk * 16384;

    float w[9];
#pragma unroll
    for (int i = 0; i < 9; i++) w[i] = convw[d * 9 + i];
    const float bias = convb[d];

    float lsum = 0.f, lsq = 0.f;
    for (int idx = threadIdx.x; idx < 16384; idx += 256) {
        const int i = idx >> 7;
        const int j = idx & 127;
        float v = bias;
#pragma unroll
        for (int u = 0; u < 3; u++) {
            const int ii = i + u - 1;
            if (ii < 0 || ii > 127) continue;
#pragma unroll
            for (int t = 0; t < 3; t++) {
                const int jj = j + t - 1;
                if (jj < 0 || jj > 127) continue;
                v += w[u * 3 + t] * plane[ii * 128 + jj];
            }
        }
        outp[idx] = v;
        lsum += v;
        lsq += v * v;
    }

    // block reduce (deterministic)
    __shared__ float ssum[8], ssq[8];
    const int lane = threadIdx.x & 31, warp = threadIdx.x >> 5;
#pragma unroll
    for (int off = 16; off > 0; off >>= 1) {
        lsum += __shfl_down_sync(0xffffffffu, lsum, off);
        lsq  += __shfl_down_sync(0xffffffffu, lsq, off);
    }
    if (lane == 0) { ssum[warp] = lsum; ssq[warp] = lsq; }
    __syncthreads();
    if (threadIdx.x == 0) {
        float s = 0.f, q = 0.f;
#pragma unroll
        for (int i = 0; i < 8; i++) { s += ssum[i]; q += ssq[i]; }
        g_psum[blk] = s;
        g_psq[blk]  = q;
    }
}

// ---------------------------------------------------------------------------
// Kernel D: finalize BatchNorm scale/shift. 1 block, 16 active threads.
// ---------------------------------------------------------------------------
__global__ void kD(const float* __restrict__ gamma, const float* __restrict__ beta)
{
    const int d = threadIdx.x;
    if (d < 16) {
        float s = 0.f, q = 0.f;
#pragma unroll
        for (int b = 0; b < 8; b++) { s += g_psum[b * 16 + d]; q += g_psq[b * 16 + d]; }
        const float invN = 1.0f / (8.0f * 16384.0f);
        const float mean = s * invN;
        const float var  = q * invN - mean * mean;
        const float rstd = rsqrtf(var + 1e-5f);
        const float sc = gamma[d] * rstd;
        g_scale[d] = sc;
        g_shift[d] = beta[d] - mean * sc;
    }
}

// ---------------------------------------------------------------------------
// Kernel E: apply affine, write output (interp is identity). float4.
// ---------------------------------------------------------------------------
__global__ void kE(float* __restrict__ out)
{
    const int i4 = blockIdx.x * 256 + threadIdx.x;   // 524288 float4s
    const int base = i4 * 4;
    const int c = (base >> 14) & 15;
    const float sc = g_scale[c], sh = g_shift[c];
    float4 v = ((const float4*)g_conved)[i4];
    v.x = v.x * sc + sh;
    v.y = v.y * sc + sh;
    v.z = v.z * sc + sh;
    v.w = v.w * sc + sh;
    ((float4*)out)[i4] = v;
}

// ---------------------------------------------------------------------------
extern "C" void kernel_launch(void* const* d_in, const int* in_sizes, int n_in,
                              void* d_out, int out_size)
{
    const float* x      = (const float*)d_in[0];
    const float* W_r    = (const float*)d_in[1];
    const float* b_r    = (const float*)d_in[2];
    const float* W_i    = (const float*)d_in[3];
    const float* b_i    = (const float*)d_in[4];
    const float* conv_w = (const float*)d_in[5];
    const float* conv_b = (const float*)d_in[6];
    const float* gamma  = (const float*)d_in[7];
    const float* beta   = (const float*)d_in[8];
    float* out = (float*)d_out;

    kA<<<16, 256>>>(W_r, W_i, b_r, b_i);
    kB<<<512, 128>>>(x);
    kC<<<128, 256>>>(conv_w, conv_b);
    kD<<<1, 32>>>(gamma, beta);
    kE<<<2048, 256>>>(out);
}

// round 2
// speedup vs baseline: 1.3289x; 1.3289x over previous
#include <cuda_runtime.h>
#include <cstdint>

// CFNO collapsed: y[n,k] = sum_j p[n,j]*A[k,j] + c[k] (FFT/Linear/IFFT folded
// into one real 16x256 map), depthwise 3x3 conv + train-mode BN, interp = id.

#define BHW  (8 * 16 * 128 * 128)

__device__ float g_At[256 * 16];    // At[j][k]
__device__ float g_c[16];
__device__ float g_img[BHW];        // linear-stage output [B,16,128,128]
__device__ float g_psum[512];       // per (plane,section) partial sums
__device__ float g_psq[512];

// ---------------------------------------------------------------------------
// Kernel A: build A^T and c. 16 blocks (one per k), 256 threads.
// ---------------------------------------------------------------------------
__global__ void kA(const float* __restrict__ Wr, const float* __restrict__ Wi,
                   const float* __restrict__ br, const float* __restrict__ bi)
{
    __shared__ float ct[256], st[256];
    __shared__ float Mr[256], Mi[256];
    const int tid = threadIdx.x;
    const int k = blockIdx.x;

    float s, c;
    sincospif(2.0f * (float)tid / 256.0f, &s, &c);
    ct[tid] = c; st[tid] = s;
    __syncthreads();

    {
        const int f = tid;
        float mr = 0.f, mi = 0.f;
#pragma unroll
        for (int d = 0; d < 16; d++) {
            const int t = ((k * d) & 15) << 4;
            const float wc = ct[t], ws = st[t];
            const float wr = Wr[d * 256 + f];
            const float wv = Wi[d * 256 + f];
            mr += wr * wc - wv * ws;
            mi += wr * ws + wv * wc;
        }
        Mr[f] = mr * (1.0f / 16.0f);
        Mi[f] = mi * (1.0f / 16.0f);
    }
    __syncthreads();

    {
        const int j = tid;
        float a0 = 0.f, a1 = 0.f, a2 = 0.f, a3 = 0.f;
#pragma unroll 4
        for (int f = 0; f < 256; f += 4) {
            a0 += Mr[f + 0] * ct[(j * (f + 0)) & 255] + Mi[f + 0] * st[(j * (f + 0)) & 255];
            a1 += Mr[f + 1] * ct[(j * (f + 1)) & 255] + Mi[f + 1] * st[(j * (f + 1)) & 255];
            a2 += Mr[f + 2] * ct[(j * (f + 2)) & 255] + Mi[f + 2] * st[(j * (f + 2)) & 255];
            a3 += Mr[f + 3] * ct[(j * (f + 3)) & 255] + Mi[f + 3] * st[(j * (f + 3)) & 255];
        }
        g_At[j * 16 + k] = (a0 + a1) + (a2 + a3);
    }

    if (tid == 0) {
        float acc = 0.f;
#pragma unroll
        for (int d = 0; d < 16; d++) {
            const int t = ((k * d) & 15) << 4;
            acc += (br[d] - bi[d]) * ct[t] - (br[d] + bi[d]) * st[t];
        }
        g_c[k] = acc * (1.0f / 16.0f);
    }
}

// ---------------------------------------------------------------------------
// Kernel B: patch GEMM with packed fma.rn.f32x2 (2 FMAs per issue slot).
// 256 threads/block, 2 adjacent patches/thread -> 512 patches/block, 256 blks.
// ---------------------------------------------------------------------------
__global__ __launch_bounds__(256) void kB(const float* __restrict__ x)
{
    __shared__ float sA[256 * 16];
    __shared__ float sc16[16];

    for (int i = threadIdx.x; i < 4096; i += 256) sA[i] = g_At[i];
    if (threadIdx.x < 16) sc16[threadIdx.x] = g_c[threadIdx.x];
    __syncthreads();

    const int p0 = blockIdx.x * 512 + threadIdx.x * 2;
    const int b  = p0 >> 14;
    const int ph = (p0 >> 7) & 127;
    const int pw = p0 & 127;

    const float* xp = x + ((size_t)(b * 2048 + ph * 16)) * 2048 + (size_t)pw * 16;

    unsigned long long acc0[8], acc1[8];
#pragma unroll
    for (int k = 0; k < 8; k++) {
        unsigned long long cp;
        asm("mov.b64 %0, {%1, %2};" : "=l"(cp) : "f"(sc16[2 * k]), "f"(sc16[2 * k + 1]));
        acc0[k] = cp; acc1[k] = cp;
    }

#pragma unroll 1
    for (int s1 = 0; s1 < 16; s1++) {
        const float4* row = (const float4*)(xp + (size_t)s1 * 2048);
        float4 q[8];
#pragma unroll
        for (int i = 0; i < 8; i++) q[i] = row[i];
        const float* p0v = (const float*)&q[0];
        const float* p1v = (const float*)&q[4];

#pragma unroll
        for (int s2 = 0; s2 < 16; s2++) {
            const ulonglong2* Ak = (const ulonglong2*)&sA[(s1 * 16 + s2) * 16];
            ulonglong2 a01 = Ak[0], a23 = Ak[1], a45 = Ak[2], a67 = Ak[3];
            unsigned long long av[8] = {a01.x, a01.y, a23.x, a23.y,
                                        a45.x, a45.y, a67.x, a67.y};
            unsigned long long v0p, v1p;
            asm("mov.b64 %0, {%1, %1};" : "=l"(v0p) : "f"(p0v[s2]));
            asm("mov.b64 %0, {%1, %1};" : "=l"(v1p) : "f"(p1v[s2]));
#pragma unroll
            for (int k = 0; k < 8; k++) {
                asm("fma.rn.f32x2 %0, %1, %2, %0;" : "+l"(acc0[k]) : "l"(v0p), "l"(av[k]));
                asm("fma.rn.f32x2 %0, %1, %2, %0;" : "+l"(acc1[k]) : "l"(v1p), "l"(av[k]));
            }
        }
    }

    const size_t ob = (size_t)b * 16 * 16384 + (size_t)ph * 128 + (size_t)pw;
#pragma unroll
    for (int k = 0; k < 8; k++) {
        float lo0, hi0, lo1, hi1;
        asm("mov.b64 {%0, %1}, %2;" : "=f"(lo0), "=f"(hi0) : "l"(acc0[k]));
        asm("mov.b64 {%0, %1}, %2;" : "=f"(lo1), "=f"(hi1) : "l"(acc1[k]));
        *(float2*)&g_img[ob + (size_t)(2 * k) * 16384]     = make_float2(lo0, lo1);
        *(float2*)&g_img[ob + (size_t)(2 * k + 1) * 16384] = make_float2(hi0, hi1);
    }
}

// ---------------------------------------------------------------------------
// Conv helper: 4 consecutive pixels of depthwise 3x3 at (i, j0..j0+3).
// ---------------------------------------------------------------------------
__device__ __forceinline__ void conv4(const float* __restrict__ plp,
                                      const float* __restrict__ w, float bias,
                                      int i, int j0, float v[4])
{
    v[0] = bias; v[1] = bias; v[2] = bias; v[3] = bias;
#pragma unroll
    for (int u = 0; u < 3; u++) {
        const int ii = i + u - 1;
        if (ii < 0 || ii > 127) continue;
        const float* row = plp + ii * 128;
        float cv[6];
        cv[0] = (j0 > 0) ? __ldg(row + j0 - 1) : 0.f;
        const float4 mid = __ldg((const float4*)(row + j0));
        cv[1] = mid.x; cv[2] = mid.y; cv[3] = mid.z; cv[4] = mid.w;
        cv[5] = (j0 + 4 < 128) ? __ldg(row + j0 + 4) : 0.f;
#pragma unroll
        for (int t = 0; t < 3; t++) {
            const float wt = w[u * 3 + t];
#pragma unroll
            for (int p = 0; p < 4; p++) v[p] += wt * cv[p + t];
        }
    }
}

// ---------------------------------------------------------------------------
// Kernel C: conv stats only. 512 blocks (plane*4+sec), 256 threads.
// ---------------------------------------------------------------------------
__global__ __launch_bounds__(256) void kC(const float* __restrict__ convw,
                                          const float* __restrict__ convb)
{
    const int plane = blockIdx.x >> 2;
    const int sec = blockIdx.x & 3;
    const int d = plane & 15;
    const float* plp = g_img + (size_t)plane * 16384;

    float w[9];
#pragma unroll
    for (int i = 0; i < 9; i++) w[i] = convw[d * 9 + i];
    const float bias = convb[d];

    float lsum = 0.f, lsq = 0.f;
#pragma unroll
    for (int t = 0; t < 4; t++) {
        const int gg = sec * 1024 + threadIdx.x + 256 * t;
        const int i = gg >> 5;
        const int j0 = (gg & 31) * 4;
        float v[4];
        conv4(plp, w, bias, i, j0, v);
#pragma unroll
        for (int p = 0; p < 4; p++) { lsum += v[p]; lsq += v[p] * v[p]; }
    }

    __shared__ float ssum[8], ssq[8];
    const int lane = threadIdx.x & 31, warp = threadIdx.x >> 5;
#pragma unroll
    for (int off = 16; off > 0; off >>= 1) {
        lsum += __shfl_down_sync(0xffffffffu, lsum, off);
        lsq  += __shfl_down_sync(0xffffffffu, lsq, off);
    }
    if (lane == 0) { ssum[warp] = lsum; ssq[warp] = lsq; }
    __syncthreads();
    if (threadIdx.x == 0) {
        float s = 0.f, q = 0.f;
#pragma unroll
        for (int i = 0; i < 8; i++) { s += ssum[i]; q += ssq[i]; }
        g_psum[blockIdx.x] = s;
        g_psq[blockIdx.x]  = q;
    }
}

// ---------------------------------------------------------------------------
// Kernel E: recompute conv, fold BN (stats reduced per-block), write out.
// ---------------------------------------------------------------------------
__global__ __launch_bounds__(256) void kE(const float* __restrict__ convw,
                                          const float* __restrict__ convb,
                                          const float* __restrict__ gamma,
                                          const float* __restrict__ beta,
                                          float* __restrict__ out)
{
    const int plane = blockIdx.x >> 2;
    const int sec = blockIdx.x & 3;
    const int d = plane & 15;

    __shared__ float s_sc, s_sh;
    if (threadIdx.x < 32) {
        const int lane = threadIdx.x;
        const int idx = (((lane >> 2) * 16 + d) << 2) + (lane & 3);
        float ps = g_psum[idx], pq = g_psq[idx];
#pragma unroll
        for (int off = 16; off > 0; off >>= 1) {
            ps += __shfl_xor_sync(0xffffffffu, ps, off);
            pq += __shfl_xor_sync(0xffffffffu, pq, off);
        }
        if (lane == 0) {
            const float invN = 1.0f / (8.0f * 16384.0f);
            const float mean = ps * invN;
            const float var  = pq * invN - mean * mean;
            const float r = rsqrtf(var + 1e-5f);
            const float scv = gamma[d] * r;
            s_sc = scv;
            s_sh = beta[d] - mean * scv;
        }
    }

    float w[9];
#pragma unroll
    for (int i = 0; i < 9; i++) w[i] = convw[d * 9 + i];
    const float bias = convb[d];
    __syncthreads();
    const float scv = s_sc, shv = s_sh;

    const float* plp = g_img + (size_t)plane * 16384;
    float* op = out + (size_t)plane * 16384;

#pragma unroll
    for (int t = 0; t < 4; t++) {
        const int gg = sec * 1024 + threadIdx.x + 256 * t;
        const int i = gg >> 5;
        const int j0 = (gg & 31) * 4;
        float v[4];
        conv4(plp, w, bias, i, j0, v);
        float4 o;
        o.x = v[0] * scv + shv;
        o.y = v[1] * scv + shv;
        o.z = v[2] * scv + shv;
        o.w = v[3] * scv + shv;
        *(float4*)(op + i * 128 + j0) = o;
    }
}

// ---------------------------------------------------------------------------
extern "C" void kernel_launch(void* const* d_in, const int* in_sizes, int n_in,
                              void* d_out, int out_size)
{
    const float* x      = (const float*)d_in[0];
    const float* W_r    = (const float*)d_in[1];
    const float* b_r    = (const float*)d_in[2];
    const float* W_i    = (const float*)d_in[3];
    const float* b_i    = (const float*)d_in[4];
    const float* conv_w = (const float*)d_in[5];
    const float* conv_b = (const float*)d_in[6];
    const float* gamma  = (const float*)d_in[7];
    const float* beta   = (const float*)d_in[8];
    float* out = (float*)d_out;

    kA<<<16, 256>>>(W_r, W_i, b_r, b_i);
    kB<<<256, 256>>>(x);
    kC<<<512, 256>>>(conv_w, conv_b);
    kE<<<512, 256>>>(conv_w, conv_b, gamma, beta, out);
}